// round 17
// baseline (speedup 1.0000x reference)
#include <cuda_runtime.h>
#include <cuda_fp16.h>

#define NP 8192
#define THREADS 256
#define IPT 2
#define IROWS (THREADS * IPT)       // 512 i's per ib
#define IB (NP / IROWS)             // 16 i-blocks
#define JC 37
#define JCHUNK 224                  // jp=112 (14*8); last chunk 128 -> jp=64 (8*8)
#define JPMAX (JCHUNK / 2)

static_assert(IB * IROWS == NP, "i coverage");
static_assert(JC * JCHUNK >= NP, "j coverage");
static_assert(IB * JC == 592, "perfect wave: 148 SMs x 4 blocks");
static_assert((JPMAX % 8) == 0 && (((NP - (JC - 1) * JCHUNK) / 2) % 8) == 0, "8-blocks");

// Scratch [jc][i]: coalesced both sides; every slot written once per launch.
__device__ float2 g_part[JC * NP];
// Per-ib arrival counters; atomicInc wraps back to 0 each launch (graph-safe).
__device__ unsigned g_sync[IB];

__device__ __forceinline__ unsigned h2u(__half2 h) {
    return *reinterpret_cast<const unsigned*>(&h);
}
__device__ __forceinline__ __half2 u2h(unsigned u) {
    return *reinterpret_cast<const __half2*>(&u);
}

#define T35   0.70020753f   // tan(35 deg)
#define INVT  1.4281480f    // 1/tan(35 deg)
// d = sqrt(x'^2+y'^2) ~= A*x' + B*|y'| on |y'|/x' in [0, tan35] (zero-mean LS fit)
// Linearity: sum(d) = A*sum(xp) + (B*T)*sum(|yb|)  -> apply coefficients once.
#define AFIT  0.96785f
#define BTFIT (0.30996f * 0.70020753f)

struct h2pair { __half2 x, y; };

__global__ __launch_bounds__(THREADS, 4)
void pair_kernel(const float2* __restrict__ past, const float2* __restrict__ pos,
                 const int* __restrict__ idxmask, const float* __restrict__ radii,
                 float* __restrict__ out) {
    __shared__ h2pair sj[JPMAX];
    __shared__ int isLast;
    const int ib = blockIdx.x;
    const int jc = blockIdx.y;
    const int tid = threadIdx.x;
    const int jbase = jc * JCHUNK;
    const int jend = min(NP - jbase, JCHUNK);   // 224 or 128
    const int jp = jend >> 1;                   // 112 or 64, multiple of 8

    const float4* __restrict__ posj4 = (const float4*)(pos + jbase);
    for (int t = tid; t < jp; t += THREADS) {
        const float4 v = posj4[t];
        sj[t].x = __floats2half2_rn(v.x, v.z);
        sj[t].y = __floats2half2_rn(v.y, v.w);
    }
    __syncthreads();

    const int i0 = ib * IROWS;
    const __half2 Z2 = __float2half2_rn(0.0f);

    __half2 hc[IPT], hs[IPT], ha[IPT], hct[IPT], hnst[IPT], hbt[IPT];
    float sumx[IPT], suma[IPT];
    unsigned cntb[IPT];

    #pragma unroll
    for (int k = 0; k < IPT; k++) {
        const int i = i0 + k * THREADS + tid;
        const float2 p = pos[i];
        const float2 q = past[i];
        const float dx = p.x - q.x;
        const float dy = p.y - q.y;
        const float l2 = fmaf(dx, dx, dy * dy);
        float rin; asm("rsqrt.approx.f32 %0, %1;" : "=f"(rin) : "f"(l2));
        const float ci = (l2 > 0.0f) ? dx * rin : 1.0f;
        const float si = (l2 > 0.0f) ? dy * rin : 0.0f;
        const float av = -fmaf(p.x, ci, p.y * si);      // -(x c + y s)
        const float bv =  fmaf(p.x, si, -(p.y * ci));   //  x s - y c
        hc[k]   = __float2half2_rn(ci);
        hs[k]   = __float2half2_rn(si);
        ha[k]   = __float2half2_rn(av);
        hct[k]  = __float2half2_rn(ci * INVT);          // y-row / tan35:
        hnst[k] = __float2half2_rn(-si * INVT);         //   arc test |yb| < xp
        hbt[k]  = __float2half2_rn(bv * INVT);
        sumx[k] = 0.0f; suma[k] = 0.0f;
        cntb[k] = 0u;
    }

    for (int base = 0; base < jp; base += 8) {
        __half2 bsx[IPT], bsa[IPT];
        #pragma unroll
        for (int k = 0; k < IPT; k++) { bsx[k] = Z2; bsa[k] = Z2; }
        #pragma unroll
        for (int mm = 0; mm < 8; mm++) {
            const int m = base + mm;
            const __half2 px = sj[m].x;
            const __half2 py = sj[m].y;
            #pragma unroll
            for (int k = 0; k < IPT; k++) {
                const __half2 xp = __hfma2(px, hc[k],  __hfma2(py, hs[k],   ha[k]));
                const __half2 yb = __hfma2(py, hct[k], __hfma2(px, hnst[k], hbt[k]));
                const unsigned aybu = h2u(yb) & 0x7FFF7FFFu;        // |yb| (alu)
                const unsigned mask = __hlt2_mask(u2h(aybu), xp);   // 0xFFFF/0 per half
                bsx[k] = __hadd2(bsx[k], u2h(mask & h2u(xp)));      // gated xp sum
                bsa[k] = __hadd2(bsa[k], u2h(mask & aybu));         // gated |yb| sum
                cntb[k] += (mask & 0x10001u);                       // per-lane count (alu)
            }
        }
        #pragma unroll
        for (int k = 0; k < IPT; k++) {               // spill fp16 block sums -> f32
            sumx[k] += __low2float(bsx[k]) + __high2float(bsx[k]);
            suma[k] += __low2float(bsa[k]) + __high2float(bsa[k]);
        }
    }

    #pragma unroll
    for (int k = 0; k < IPT; k++) {
        const int i = i0 + k * THREADS + tid;
        float sx = sumx[k], sa = suma[k];
        float c = (float)((cntb[k] & 0xFFFFu) + (cntb[k] >> 16));
        if (i >= jbase && i < jbase + jend) {
            // Remove self-pair via identical lanewise recompute.
            const int loc = i - jbase;
            const int m = loc >> 1, lane = loc & 1;
            const __half2 px = sj[m].x, py = sj[m].y;
            const __half2 xp = __hfma2(px, hc[k],  __hfma2(py, hs[k],   ha[k]));
            const __half2 yb = __hfma2(py, hct[k], __hfma2(px, hnst[k], hbt[k]));
            const unsigned aybu = h2u(yb) & 0x7FFF7FFFu;
            const unsigned mask = __hlt2_mask(u2h(aybu), xp);
            const __half2 gx = u2h(mask & h2u(xp));
            const __half2 ga = u2h(mask & aybu);
            if (lane) { sx -= __high2float(gx); sa -= __high2float(ga);
                        c -= (float)((mask >> 16) & 1u); }
            else      { sx -= __low2float(gx);  sa -= __low2float(ga);
                        c -= (float)(mask & 1u); }
        }
        const float s = fmaf(AFIT, sx, BTFIT * sa);   // apply fit coefficients once
        g_part[jc * NP + i] = make_float2(s, c);      // coalesced
    }

    // ── fused finalize: last jc-block for this ib reduces all partials ──
    __threadfence();                       // publish g_part writes
    __syncthreads();                       // all warps done writing
    if (tid == 0)
        isLast = (atomicInc(&g_sync[ib], JC - 1) == JC - 1);  // wraps to 0 per launch
    __syncthreads();
    if (isLast) {
        // Each thread reduces 2 adjacent rows via LDG.128 (coalesced, high MLP).
        const int i = i0 + tid * 2;
        float sA = 0.0f, cA = 0.0f, sB = 0.0f, cB = 0.0f;
        #pragma unroll
        for (int q = 0; q < JC; q++) {
            const float4 v = *(const float4*)&g_part[q * NP + i];  // {sA,cA,sB,cB}
            sA += v.x; cA += v.y;
            sB += v.z; cB += v.w;
        }
        float meanA = (cA > 0.0f) ? sA / cA : 0.0f;
        float meanB = (cB > 0.0f) ? sB / cB : 0.0f;
        meanA = fminf(fmaxf(meanA, 0.2f), 5.0f);
        meanB = fminf(fmaxf(meanB, 0.2f), 5.0f);
        const float rA = fmaf((meanA - 0.2f) * (1.0f / 4.8f), 3.5f, 0.5f);
        const float rB = fmaf((meanB - 0.2f) * (1.0f / 4.8f), 3.5f, 0.5f);
        out[i]     = idxmask[i]     ? rA : radii[i];
        out[i + 1] = idxmask[i + 1] ? rB : radii[i + 1];
    }
}

extern "C" void kernel_launch(void* const* d_in, const int* in_sizes, int n_in,
                              void* d_out, int out_size) {
    const float2* past = (const float2*)d_in[0];
    const float2* pos  = (const float2*)d_in[1];
    const int* idxm    = (const int*)d_in[2];   // bool widened to int32
    const float* radii = (const float*)d_in[3];
    float* out = (float*)d_out;

    dim3 grid(IB, JC);
    pair_kernel<<<grid, THREADS>>>(past, pos, idxm, radii, out);
}